// round 1
// baseline (speedup 1.0000x reference)
#include <cuda_runtime.h>
#include <cuda_bf16.h>
#include <math.h>

#define Bc 8
#define N1c 4096
#define N2c 2048
#define Hc 64
#define Kc 8

// ---------------- device scratch (no cudaMalloc allowed) ----------------
__device__ float    g_h1 [Bc*N1c*Hc];
__device__ float    g_x2a[Bc*N1c];
__device__ int      g_nbr1[Bc*N1c*Kc];
__device__ float    g_Pd1[Bc*N1c*96];
__device__ float    g_Ps1[Bc*N1c*96];
__device__ unsigned g_agg1[Bc*N1c*Hc];
__device__ float    g_h3 [Bc*N2c*Hc];
__device__ float    g_x2b[Bc*N2c];
__device__ int      g_nbr2[Bc*N2c*Kc];
__device__ float    g_Pd2[Bc*N2c*96];
__device__ float    g_Ps2[Bc*N2c*96];
__device__ unsigned g_agg2[Bc*N2c*Hc];

// ---------------- helpers ----------------
__device__ __forceinline__ float eluf(float x) { return x > 0.f ? x : expm1f(x); }

// order-preserving float -> uint encoding (monotone), so atomicMax works.
__device__ __forceinline__ unsigned encf(float f) {
    unsigned u = __float_as_uint(f);
    return (u & 0x80000000u) ? ~u : (u | 0x80000000u);
}
__device__ __forceinline__ float decf(unsigned u) {
    return __uint_as_float((u & 0x80000000u) ? (u ^ 0x80000000u) : ~u);
}

// ---------------- zero init ----------------
__global__ void zero_kernel(unsigned* p, int n) {
    for (int i = blockIdx.x * blockDim.x + threadIdx.x; i < n; i += gridDim.x * blockDim.x)
        p[i] = 0u;
}

// ---------------- input MLP: x*norm -> elu(10->32) -> elu(32->64), + sq-norm ----------------
__global__ void input_mlp_kernel(const float* __restrict__ x, const float* __restrict__ nrm,
                                 const float* __restrict__ w1, const float* __restrict__ b1,
                                 const float* __restrict__ w2, const float* __restrict__ b2,
                                 float* __restrict__ h, float* __restrict__ x2) {
    __shared__ float sw1[10 * 32], sb1[32], sw2[32 * 64], sb2[64], snrm[10];
    for (int idx = threadIdx.x; idx < 320; idx += blockDim.x) sw1[idx] = w1[idx];
    for (int idx = threadIdx.x; idx < 2048; idx += blockDim.x) sw2[idx] = w2[idx];
    if (threadIdx.x < 32) sb1[threadIdx.x] = b1[threadIdx.x];
    if (threadIdx.x < 64) sb2[threadIdx.x] = b2[threadIdx.x];
    if (threadIdx.x < 10) snrm[threadIdx.x] = nrm[threadIdx.x];
    __syncthreads();
    int n = blockIdx.x * blockDim.x + threadIdx.x;  // 0..B*N1-1
    float xv[10];
#pragma unroll
    for (int c = 0; c < 10; c++) xv[c] = x[n * 10 + c] * snrm[c];
    float a[32];
#pragma unroll
    for (int o = 0; o < 32; o++) {
        float acc = sb1[o];
#pragma unroll
        for (int c = 0; c < 10; c++) acc = fmaf(xv[c], sw1[c * 32 + o], acc);
        a[o] = eluf(acc);
    }
    float ss = 0.f;
#pragma unroll 4
    for (int o = 0; o < 64; o++) {
        float acc = sb2[o];
#pragma unroll
        for (int c = 0; c < 32; c++) acc = fmaf(a[c], sw2[c * 64 + o], acc);
        acc = eluf(acc);
        h[(size_t)n * 64 + o] = acc;
        ss = fmaf(acc, acc, ss);
    }
    x2[n] = ss;
}

// ---------------- brute-force kNN (k=8 smallest squared dists, self excluded) ----------------
template <int N>
__global__ void __launch_bounds__(128) knn_kernel(const float* __restrict__ h,
                                                  const float* __restrict__ x2,
                                                  int* __restrict__ nbr) {
    __shared__ float sh[128 * 64];
    __shared__ float sx2[128];
    const int b = blockIdx.y;
    const int i = blockIdx.x * 128 + threadIdx.x;
    const float* hb = h + (size_t)b * N * 64;
    float q[64];
#pragma unroll
    for (int c = 0; c < 64; c++) q[c] = hb[(size_t)i * 64 + c];
    const float x2i = x2[b * N + i];
    float best[8];
    int bidx[8];
#pragma unroll
    for (int r = 0; r < 8; r++) { best[r] = 3e38f; bidx[r] = 0; }

    for (int jt = 0; jt < N; jt += 128) {
        for (int idx = threadIdx.x; idx < 128 * 64; idx += 128)
            sh[idx] = hb[(size_t)jt * 64 + idx];
        sx2[threadIdx.x] = x2[b * N + jt + threadIdx.x];
        __syncthreads();
#pragma unroll 1
        for (int jj = 0; jj < 128; jj++) {
            const float* rr = &sh[jj * 64];
            float a0 = 0.f, a1 = 0.f, a2 = 0.f, a3 = 0.f;
#pragma unroll
            for (int c = 0; c < 64; c += 4) {
                a0 = fmaf(q[c + 0], rr[c + 0], a0);
                a1 = fmaf(q[c + 1], rr[c + 1], a1);
                a2 = fmaf(q[c + 2], rr[c + 2], a2);
                a3 = fmaf(q[c + 3], rr[c + 3], a3);
            }
            int j = jt + jj;
            float d = x2i + sx2[jj] - 2.f * ((a0 + a1) + (a2 + a3));
            if (d < best[7] && j != i) {
                best[7] = d; bidx[7] = j;
#pragma unroll
                for (int r = 7; r > 0; --r) {
                    if (best[r] < best[r - 1]) {
                        float tb = best[r]; best[r] = best[r - 1]; best[r - 1] = tb;
                        int ti = bidx[r]; bidx[r] = bidx[r - 1]; bidx[r - 1] = ti;
                    }
                }
            }
        }
        __syncthreads();
    }
#pragma unroll
    for (int r = 0; r < 8; r++) nbr[((size_t)(b * N + i)) * 8 + r] = bidx[r];
}

// ---------------- per-node projections for EdgeConv layer 1 decomposition ----------------
// P_d = X @ (W1_top - W1_bot),  P_s = X @ W1_bot   (bias added later)
__global__ void proj_kernel(const float* __restrict__ h, const float* __restrict__ wa,
                            float* __restrict__ Pd, float* __restrict__ Ps, int NB) {
    __shared__ float Wd[64 * 96];
    __shared__ float Ws[64 * 96];
    for (int idx = threadIdx.x; idx < 64 * 96; idx += blockDim.x) {
        float top = wa[idx];
        float bot = wa[64 * 96 + idx];
        Wd[idx] = top - bot;
        Ws[idx] = bot;
    }
    __syncthreads();
    int warp = (blockIdx.x * blockDim.x + threadIdx.x) >> 5;
    int lane = threadIdx.x & 31;
    int nwarps = (gridDim.x * blockDim.x) >> 5;
    for (int n = warp; n < NB; n += nwarps) {
        float h0 = h[(size_t)n * 64 + lane];
        float h1 = h[(size_t)n * 64 + 32 + lane];
        float d0 = 0, d1 = 0, d2 = 0, s0 = 0, s1 = 0, s2 = 0;
#pragma unroll
        for (int c = 0; c < 64; c++) {
            float hc = __shfl_sync(0xffffffffu, (c < 32) ? h0 : h1, c & 31);
            const float* wd = &Wd[c * 96 + lane];
            const float* ws = &Ws[c * 96 + lane];
            d0 = fmaf(hc, wd[0], d0);  d1 = fmaf(hc, wd[32], d1);  d2 = fmaf(hc, wd[64], d2);
            s0 = fmaf(hc, ws[0], s0);  s1 = fmaf(hc, ws[32], s1);  s2 = fmaf(hc, ws[64], s2);
        }
        Pd[(size_t)n * 96 + lane] = d0; Pd[(size_t)n * 96 + lane + 32] = d1; Pd[(size_t)n * 96 + lane + 64] = d2;
        Ps[(size_t)n * 96 + lane] = s0; Ps[(size_t)n * 96 + lane + 32] = s1; Ps[(size_t)n * 96 + lane + 64] = s2;
    }
}

// ---------------- EdgeConv: hidden = elu(Pd[i]+Ps[j]+b1); out = elu(hidden@W2+b2); scatter-max ----------------
__global__ void __launch_bounds__(256) edgeconv_kernel(
    const float* __restrict__ Pd, const float* __restrict__ Ps,
    const float* __restrict__ b1, const float* __restrict__ w2,
    const float* __restrict__ b2, const int* __restrict__ nbr,
    unsigned* __restrict__ agg, int Nn) {
    __shared__ float W2s[96 * 64];
    __shared__ float b2s[64];
    __shared__ float hidF[8][96];
    __shared__ float hidR[8][96];
    for (int idx = threadIdx.x; idx < 96 * 64; idx += blockDim.x) W2s[idx] = w2[idx];
    if (threadIdx.x < 64) b2s[threadIdx.x] = b2[threadIdx.x];
    __syncthreads();
    const int w = threadIdx.x >> 5, lane = threadIdx.x & 31;
    const int gn = blockIdx.x * 8 + w;       // global node = b*Nn + i
    const int b = gn / Nn;
    const float* pdi_p = Pd + (size_t)gn * 96;
    const float* psi_p = Ps + (size_t)gn * 96;
    float pdi0 = pdi_p[lane], pdi1 = pdi_p[lane + 32], pdi2 = pdi_p[lane + 64];
    float psi0 = psi_p[lane], psi1 = psi_p[lane + 32], psi2 = psi_p[lane + 64];
    float b10 = b1[lane], b11 = b1[lane + 32], b12 = b1[lane + 64];
    int nk = (lane < 8) ? nbr[(size_t)gn * 8 + lane] : 0;
    unsigned fm0 = 0u, fm1 = 0u;
#pragma unroll 1
    for (int k = 0; k < 8; k++) {
        int j = __shfl_sync(0xffffffffu, nk, k);
        size_t jg = (size_t)b * Nn + j;
        const float* pdj = Pd + jg * 96;
        const float* psj = Ps + jg * 96;
        float pj0 = pdj[lane], pj1 = pdj[lane + 32], pj2 = pdj[lane + 64];
        float sj0 = psj[lane], sj1 = psj[lane + 32], sj2 = psj[lane + 64];
        hidF[w][lane]      = eluf(pdi0 + sj0 + b10);
        hidF[w][lane + 32] = eluf(pdi1 + sj1 + b11);
        hidF[w][lane + 64] = eluf(pdi2 + sj2 + b12);
        hidR[w][lane]      = eluf(pj0 + psi0 + b10);
        hidR[w][lane + 32] = eluf(pj1 + psi1 + b11);
        hidR[w][lane + 64] = eluf(pj2 + psi2 + b12);
        __syncwarp();
        float aF0 = b2s[lane], aF1 = b2s[lane + 32];
        float aR0 = aF0, aR1 = aF1;
#pragma unroll 8
        for (int hh = 0; hh < 96; hh++) {
            float vf = hidF[w][hh], vr = hidR[w][hh];
            float w0 = W2s[hh * 64 + lane], w1 = W2s[hh * 64 + lane + 32];
            aF0 = fmaf(vf, w0, aF0); aF1 = fmaf(vf, w1, aF1);
            aR0 = fmaf(vr, w0, aR0); aR1 = fmaf(vr, w1, aR1);
        }
        __syncwarp();
        unsigned e0 = encf(eluf(aF0)), e1 = encf(eluf(aF1));
        fm0 = max(fm0, e0); fm1 = max(fm1, e1);
        atomicMax(agg + jg * 64 + lane,      encf(eluf(aR0)));
        atomicMax(agg + jg * 64 + lane + 32, encf(eluf(aR1)));
    }
    atomicMax(agg + (size_t)gn * 64 + lane,      fm0);
    atomicMax(agg + (size_t)gn * 64 + lane + 32, fm1);
}

// ---------------- decode + pairwise max pool + sq-norm ----------------
__global__ void pool_kernel(const unsigned* __restrict__ agg, float* __restrict__ h3,
                            float* __restrict__ x2b) {
    int w = (blockIdx.x * blockDim.x + threadIdx.x) >> 5;  // out node global over B*N2
    int lane = threadIdx.x & 31;
    int b = w / N2c;
    int i = w - b * N2c;
    size_t s0 = ((size_t)(b * N1c + 2 * i)) * 64;
    float ss = 0.f;
#pragma unroll
    for (int r = 0; r < 2; r++) {
        int c = lane + 32 * r;
        float v = fmaxf(decf(agg[s0 + c]), decf(agg[s0 + 64 + c]));
        h3[(size_t)w * 64 + c] = v;
        ss = fmaf(v, v, ss);
    }
    for (int o = 16; o > 0; o >>= 1) ss += __shfl_down_sync(0xffffffffu, ss, o);
    if (lane == 0) x2b[w] = ss;
}

// ---------------- global max pool + head MLP + output heads ----------------
__global__ void final_kernel(const unsigned* __restrict__ agg,
                             const float* __restrict__ w1, const float* __restrict__ bb1,
                             const float* __restrict__ w2, const float* __restrict__ bb2,
                             const float* __restrict__ w3, const float* __restrict__ bb3,
                             float* __restrict__ out) {
    __shared__ float red[256];
    __shared__ float gv[64], t1[64], t2[32];
    int b = blockIdx.x;
    int c = threadIdx.x & 63, grp = threadIdx.x >> 6;
    float m = -3e38f;
    for (int n = grp; n < N2c; n += 4)
        m = fmaxf(m, decf(agg[((size_t)(b * N2c + n)) * 64 + c]));
    red[threadIdx.x] = m;
    __syncthreads();
    if (threadIdx.x < 64) {
        m = fmaxf(fmaxf(red[threadIdx.x], red[threadIdx.x + 64]),
                  fmaxf(red[threadIdx.x + 128], red[threadIdx.x + 192]));
        gv[threadIdx.x] = m;
    }
    __syncthreads();
    if (threadIdx.x < 64) {
        float acc = bb1[threadIdx.x];
#pragma unroll
        for (int cc = 0; cc < 64; cc++) acc = fmaf(gv[cc], w1[cc * 64 + threadIdx.x], acc);
        t1[threadIdx.x] = eluf(acc);
    }
    __syncthreads();
    if (threadIdx.x < 32) {
        float acc = bb2[threadIdx.x];
#pragma unroll
        for (int cc = 0; cc < 64; cc++) acc = fmaf(t1[cc], w2[cc * 32 + threadIdx.x], acc);
        t2[threadIdx.x] = eluf(acc);
    }
    __syncthreads();
    if (threadIdx.x == 0) {
        float o0 = bb3[0], o1 = bb3[1];
#pragma unroll
        for (int cc = 0; cc < 32; cc++) {
            o0 = fmaf(t2[cc], w3[cc * 2 + 0], o0);
            o1 = fmaf(t2[cc], w3[cc * 2 + 1], o1);
        }
        float met = fmaxf(o0, 0.f) + log1pf(expf(-fabsf(o0)));     // stable softplus
        float sig = 1.f / (1.f + expf(-o1));
        float phi = 3.14159265358979323846f * (2.f * sig - 1.f);
        out[b * 2 + 0] = met;
        out[b * 2 + 1] = phi;
    }
}

// ---------------- launch ----------------
extern "C" void kernel_launch(void* const* d_in, const int* in_sizes, int n_in,
                              void* d_out, int out_size) {
    const float* x      = (const float*)d_in[0];
    const float* nrm    = (const float*)d_in[1];
    const float* w_in1  = (const float*)d_in[2];
    const float* b_in1  = (const float*)d_in[3];
    const float* w_in2  = (const float*)d_in[4];
    const float* b_in2  = (const float*)d_in[5];
    const float* w_c1a  = (const float*)d_in[6];
    const float* b_c1a  = (const float*)d_in[7];
    const float* w_c1b  = (const float*)d_in[8];
    const float* b_c1b  = (const float*)d_in[9];
    const float* w_c2a  = (const float*)d_in[10];
    const float* b_c2a  = (const float*)d_in[11];
    const float* w_c2b  = (const float*)d_in[12];
    const float* b_c2b  = (const float*)d_in[13];
    const float* w_o1   = (const float*)d_in[14];
    const float* b_o1   = (const float*)d_in[15];
    const float* w_o2   = (const float*)d_in[16];
    const float* b_o2   = (const float*)d_in[17];
    const float* w_o3   = (const float*)d_in[18];
    const float* b_o3   = (const float*)d_in[19];
    float* out = (float*)d_out;

    float *h1, *x2a, *Pd1, *Ps1, *h3, *x2b, *Pd2, *Ps2;
    int *nbr1, *nbr2;
    unsigned *agg1, *agg2;
    cudaGetSymbolAddress((void**)&h1,   g_h1);
    cudaGetSymbolAddress((void**)&x2a,  g_x2a);
    cudaGetSymbolAddress((void**)&nbr1, g_nbr1);
    cudaGetSymbolAddress((void**)&Pd1,  g_Pd1);
    cudaGetSymbolAddress((void**)&Ps1,  g_Ps1);
    cudaGetSymbolAddress((void**)&agg1, g_agg1);
    cudaGetSymbolAddress((void**)&h3,   g_h3);
    cudaGetSymbolAddress((void**)&x2b,  g_x2b);
    cudaGetSymbolAddress((void**)&nbr2, g_nbr2);
    cudaGetSymbolAddress((void**)&Pd2,  g_Pd2);
    cudaGetSymbolAddress((void**)&Ps2,  g_Ps2);
    cudaGetSymbolAddress((void**)&agg2, g_agg2);

    zero_kernel<<<1024, 256>>>(agg1, Bc * N1c * Hc);
    zero_kernel<<<1024, 256>>>(agg2, Bc * N2c * Hc);

    input_mlp_kernel<<<(Bc * N1c) / 128, 128>>>(x, nrm, w_in1, b_in1, w_in2, b_in2, h1, x2a);

    knn_kernel<N1c><<<dim3(N1c / 128, Bc), 128>>>(h1, x2a, nbr1);
    proj_kernel<<<(Bc * N1c) / 8, 256>>>(h1, w_c1a, Pd1, Ps1, Bc * N1c);
    edgeconv_kernel<<<(Bc * N1c) / 8, 256>>>(Pd1, Ps1, b_c1a, w_c1b, b_c1b, nbr1, agg1, N1c);

    pool_kernel<<<(Bc * N2c) / 8, 256>>>(agg1, h3, x2b);

    knn_kernel<N2c><<<dim3(N2c / 128, Bc), 128>>>(h3, x2b, nbr2);
    proj_kernel<<<(Bc * N2c) / 8, 256>>>(h3, w_c2a, Pd2, Ps2, Bc * N2c);
    edgeconv_kernel<<<(Bc * N2c) / 8, 256>>>(Pd2, Ps2, b_c2a, w_c2b, b_c2b, nbr2, agg2, N2c);

    final_kernel<<<Bc, 256>>>(agg2, w_o1, b_o1, w_o2, b_o2, w_o3, b_o3, out);
}